// round 15
// baseline (speedup 1.0000x reference)
#include <cuda_runtime.h>
#include <math.h>
#include <stdint.h>

#define BATCH   8
#define SEQLEN  2048
#define DMODEL  1024
#define HALF    1024
#define DINNER  2048
#define DSTATE  16
#define DTRANK  64
#define XDBL    96          // DTRANK + 2*DSTATE
#define NTOK    (BATCH*SEQLEN)   // 16384

#define ZSPLIT1 248         // z-GEMM blocks fused with xproj (of 1024)

// ---------------- scratch (static device globals: allocation-guard safe) ----
static __device__ float g_xz   [(size_t)NTOK * DINNER];  // xz = x @ W_in
static __device__ float g_xh   [(size_t)NTOK * HALF];    // silu(conv(xh))
static __device__ float g_delta[(size_t)NTOK * HALF];    // softplus(dt)
static __device__ float g_xdbl [(size_t)NTOK * XDBL];    // [dt_r | B | C]
static __device__ float g_ycat [(size_t)NTOK * DINNER];  // [y | silu(conv(z))]
static __device__ float g_A    [HALF * DSTATE];          // -exp(A_log)

// ---------------- helpers ---------------------------------------------------
__device__ __forceinline__ float siluf(float v) {
    return v / (1.0f + __expf(-v));
}
__device__ __forceinline__ unsigned long long pack2(float x, float y) {
    unsigned long long r;
    asm("mov.b64 %0, {%1, %2};" : "=l"(r) : "f"(x), "f"(y));
    return r;
}
__device__ __forceinline__ void fma2(unsigned long long& d,
                                     unsigned long long a, unsigned long long b) {
    asm("fma.rn.f32x2 %0, %1, %2, %0;" : "+l"(d) : "l"(a), "l"(b));
}
__device__ __forceinline__ float2 unpack2(unsigned long long v) {
    float x, y;
    asm("mov.b64 {%0, %1}, %2;" : "=f"(x), "=f"(y) : "l"(v));
    return make_float2(x, y);
}

// ---------------- A = -exp(A_log) -------------------------------------------
__global__ void aprep_k(const float* __restrict__ A_log) {
    int i = blockIdx.x * blockDim.x + threadIdx.x;
    if (i < HALF * DSTATE) g_A[i] = -__expf(A_log[i]);
}

// ---------------- 128x128x16 register-blocked SGEMM core (f32x2 math) -------
// C[bm:+128, bn:+128] (+)= A[M,K](lda) @ B[K,N] (+ bias). smem via pointers.
__device__ __forceinline__ void sgemm_core(
    float* __restrict__ As, float* __restrict__ Bs,      // 2112 + 2048 floats
    const float* __restrict__ A, int lda,
    const float* __restrict__ B,
    const float* __restrict__ bias, float* __restrict__ C, int accum,
    int bm, int bn, int N, int K)
{
    const int BK = 16;
    int tid = threadIdx.x;
    int tx = tid & 15;
    int ty = tid >> 4;

    unsigned long long acc2[8][4];
#pragma unroll
    for (int i = 0; i < 8; i++)
#pragma unroll
        for (int j = 0; j < 4; j++) acc2[i][j] = 0ULL;

    int a_row = tid >> 2;
    int a_col = (tid & 3) << 2;
    int b_row = tid >> 5;
    int b_col = (tid & 31) << 2;

    const float* Aptr = A + (size_t)bm * lda;
    const float* Bptr = B + bn;

    for (int k0 = 0; k0 < K; k0 += BK) {
#pragma unroll
        for (int r = 0; r < 2; r++) {
            int row = a_row + r * 64;
            float4 v = *(const float4*)(Aptr + (size_t)row * lda + k0 + a_col);
            As[(a_col + 0) * 132 + row] = v.x;
            As[(a_col + 1) * 132 + row] = v.y;
            As[(a_col + 2) * 132 + row] = v.z;
            As[(a_col + 3) * 132 + row] = v.w;
        }
#pragma unroll
        for (int r = 0; r < 2; r++) {
            int row = b_row + r * 8;
            *(float4*)(&Bs[row * 128 + b_col]) =
                *(const float4*)(Bptr + (size_t)(k0 + row) * N + b_col);
        }
        __syncthreads();

#pragma unroll
        for (int k = 0; k < BK; k++) {
            float4 a0 = *(const float4*)(&As[k * 132 + ty * 8]);
            float4 a1 = *(const float4*)(&As[k * 132 + ty * 8 + 4]);
            float4 b0 = *(const float4*)(&Bs[k * 128 + tx * 8]);
            float4 b1 = *(const float4*)(&Bs[k * 128 + tx * 8 + 4]);
            unsigned long long bp[4];
            bp[0] = pack2(b0.x, b0.y);
            bp[1] = pack2(b0.z, b0.w);
            bp[2] = pack2(b1.x, b1.y);
            bp[3] = pack2(b1.z, b1.w);
            float af[8] = {a0.x, a0.y, a0.z, a0.w, a1.x, a1.y, a1.z, a1.w};
#pragma unroll
            for (int i = 0; i < 8; i++) {
                unsigned long long ap = pack2(af[i], af[i]);
                fma2(acc2[i][0], ap, bp[0]);
                fma2(acc2[i][1], ap, bp[1]);
                fma2(acc2[i][2], ap, bp[2]);
                fma2(acc2[i][3], ap, bp[3]);
            }
        }
        __syncthreads();
    }

#pragma unroll
    for (int i = 0; i < 8; i++) {
        int row = bm + ty * 8 + i;
#pragma unroll
        for (int j = 0; j < 2; j++) {
            int col = bn + tx * 8 + j * 4;
            float2 p0 = unpack2(acc2[i][j * 2]);
            float2 p1 = unpack2(acc2[i][j * 2 + 1]);
            float4 v = make_float4(p0.x, p0.y, p1.x, p1.y);
            float* cp = C + (size_t)row * N + col;
            if (accum) {
                float4 c = *(float4*)cp;
                v.x += c.x; v.y += c.y; v.z += c.z; v.w += c.w;
            }
            if (bias) {
                v.x += bias[col];   v.y += bias[col+1];
                v.z += bias[col+2]; v.w += bias[col+3];
            }
            *(float4*)cp = v;
        }
    }
}

// z-GEMM block g (0..1023): out[bm,bn] = z @ W_out[HALF:] + b_out
__device__ __forceinline__ void gemm_z_blk(
    float* As, float* Bs, int g,
    const float* __restrict__ W_out, const float* __restrict__ b_out,
    float* __restrict__ out)
{
    int bn = (g & 7) * 128;
    int bm = (g >> 3) * 128;
    sgemm_core(As, Bs, g_ycat + HALF, DINNER, W_out + (size_t)HALF * DMODEL,
               b_out, out, 0, bm, bn, DMODEL, HALF);
}

__global__ __launch_bounds__(256) void gemm_in_k(
    const float* __restrict__ x, const float* __restrict__ W_in)
{
    __shared__ float As[16 * 132];
    __shared__ float Bs[16 * 128];
    sgemm_core(As, Bs, x, DMODEL, W_in, nullptr, g_xz, 0,
               blockIdx.y * 128, blockIdx.x * 128, DINNER, DMODEL);
}

// out += y @ W_out[:HALF, :]
__global__ __launch_bounds__(256) void gemm_y_k(
    const float* __restrict__ W_out, float* __restrict__ out)
{
    __shared__ float As[16 * 132];
    __shared__ float Bs[16 * 128];
    sgemm_core(As, Bs, g_ycat, DINNER, W_out, nullptr, out, 1,
               blockIdx.y * 128, blockIdx.x * 128, DMODEL, HALF);
}

// ---------------- depthwise conv1d(width 4, SAME: pad_lo=1) + SiLU ----------
__global__ __launch_bounds__(256) void conv_silu_k(
    const float* __restrict__ kx, const float* __restrict__ kz)
{
    int idx = blockIdx.x * 256 + threadIdx.x;       // over NTOK*HALF
    int c  = idx & (HALF - 1);
    int bl = idx >> 10;
    int l  = bl & (SEQLEN - 1);

    float accx = 0.0f, accz = 0.0f;
    const float* base = g_xz + (size_t)bl * DINNER;
#pragma unroll
    for (int w = 0; w < 4; w++) {
        int dl = w - 1;
        int ll = l + dl;
        if (ll >= 0 && ll < SEQLEN) {
            const float* p = base + (ptrdiff_t)dl * DINNER;
            accx = fmaf(p[c],        kx[w * HALF + c], accx);
            accz = fmaf(p[HALF + c], kz[w * HALF + c], accz);
        }
    }
    g_xh  [(size_t)bl * HALF   + c]        = siluf(accx);
    g_ycat[(size_t)bl * DINNER + HALF + c] = siluf(accz);
}

// ---------------- xproj body: 128-row tile, 8x6 per-thread (proven R9) -------
__device__ __forceinline__ void xproj_blk(
    float* __restrict__ As /*32*128*/, float* __restrict__ Ws /*32*96*/,
    int blk, const float* __restrict__ W)
{
    int tid = threadIdx.x;
    int bm = blk * 128;
    int tx = tid & 15;   // 6 cols each
    int ty = tid >> 4;   // 8 rows each

    float acc[8][6];
#pragma unroll
    for (int i = 0; i < 8; i++)
#pragma unroll
        for (int j = 0; j < 6; j++) acc[i][j] = 0.0f;

    for (int k0 = 0; k0 < HALF; k0 += 32) {
        for (int i = tid; i < 128 * 32; i += 256) {
            int m = i >> 5, k = i & 31;
            As[k * 128 + m] = g_xh[(size_t)(bm + m) * HALF + k0 + k];
        }
        for (int i = tid; i < 32 * 96; i += 256) {
            int k = i / 96, n = i - k * 96;
            Ws[k * 96 + n] = W[(size_t)(k0 + k) * XDBL + n];
        }
        __syncthreads();
#pragma unroll 8
        for (int k = 0; k < 32; k++) {
            float af[8], wf[6];
#pragma unroll
            for (int i = 0; i < 8; i++) af[i] = As[k * 128 + ty * 8 + i];
#pragma unroll
            for (int j = 0; j < 6; j++) wf[j] = Ws[k * 96 + tx * 6 + j];
#pragma unroll
            for (int i = 0; i < 8; i++)
#pragma unroll
                for (int j = 0; j < 6; j++)
                    acc[i][j] = fmaf(af[i], wf[j], acc[i][j]);
        }
        __syncthreads();
    }
#pragma unroll
    for (int i = 0; i < 8; i++)
#pragma unroll
        for (int j = 0; j < 6; j++)
            g_xdbl[(size_t)(bm + ty * 8 + i) * XDBL + tx * 6 + j] = acc[i][j];
}

// ---------------- fused1: xproj (128 blocks) || z-GEMM slice A ----------------
__global__ __launch_bounds__(256) void fused1_k(
    const float* __restrict__ W_xproj,
    const float* __restrict__ W_out, const float* __restrict__ b_out,
    float* __restrict__ out)
{
    __shared__ float smem[32 * 128 + 32 * 96];   // 7168 floats (>= 2112+2048)
    if (blockIdx.x < 128) {
        xproj_blk(smem, smem + 32 * 128, blockIdx.x, W_xproj);
    } else {
        gemm_z_blk(smem, smem + 16 * 132, blockIdx.x - 128, W_out, b_out, out);
    }
}

// ---------------- delta = softplus(x_dbl[:, :64] @ W_dt + 2*b_dt) -----------
__global__ __launch_bounds__(256) void dtproj_k(
    const float* __restrict__ Wdt, const float* __restrict__ bdt)
{
    __shared__ float As[64 * 64];
    __shared__ float Ws[64 * 64];
    int tid = threadIdx.x;
    int bm = blockIdx.y * 64;
    int bn = blockIdx.x * 64;
    int tx = tid & 15;
    int ty = tid >> 4;

    for (int i = tid; i < 64 * 64; i += 256) {
        int m = i >> 6, k = i & 63;
        As[k * 64 + m] = g_xdbl[(size_t)(bm + m) * XDBL + k];
    }
    for (int i = tid; i < 64 * 64; i += 256) {
        int k = i >> 6, n = i & 63;
        Ws[k * 64 + n] = Wdt[(size_t)k * HALF + bn + n];
    }
    __syncthreads();

    float acc[4][4];
#pragma unroll
    for (int i = 0; i < 4; i++)
#pragma unroll
        for (int j = 0; j < 4; j++) acc[i][j] = 0.0f;

#pragma unroll 16
    for (int k = 0; k < 64; k++) {
        float af[4], wf[4];
#pragma unroll
        for (int i = 0; i < 4; i++) af[i] = As[k * 64 + ty * 4 + i];
#pragma unroll
        for (int j = 0; j < 4; j++) wf[j] = Ws[k * 64 + tx * 4 + j];
#pragma unroll
        for (int i = 0; i < 4; i++)
#pragma unroll
            for (int j = 0; j < 4; j++)
                acc[i][j] = fmaf(af[i], wf[j], acc[i][j]);
    }

#pragma unroll
    for (int i = 0; i < 4; i++) {
        int row = bm + ty * 4 + i;
#pragma unroll
        for (int j = 0; j < 4; j++) {
            int col = bn + tx * 4 + j;
            float v = acc[i][j] + 2.0f * bdt[col];
            float sp = (v > 25.0f) ? v : log1pf(__expf(v));
            g_delta[(size_t)row * HALF + col] = sp;
        }
    }
}

// ---------------- scan body: 2 dd-streams per thread (256 blocks) ------------
__device__ __forceinline__ void scan_blk(int sb, const float* __restrict__ Dvec)
{
    int tid = threadIdx.x;
    int n   = tid & 15;
    int idx = tid >> 4;                 // 0..15
    int b   = sb >> 5;                  // 0..7
    int dd0 = (sb & 31) * 32 + idx;     // first dd
    int dd1 = dd0 + 16;                 // second dd

    float a0 = g_A[dd0 * DSTATE + n];
    float a1 = g_A[dd1 * DSTATE + n];
    float D0 = Dvec[dd0], D1 = Dvec[dd1];
    float h0 = 0.0f, h1 = 0.0f;

    const float* up  = g_xh    + (size_t)b * SEQLEN * HALF;
    const float* dtp = g_delta + (size_t)b * SEQLEN * HALF;
    const float* bp  = g_xdbl  + (size_t)b * SEQLEN * XDBL + DTRANK + n;
    float*       yp  = g_ycat  + (size_t)b * SEQLEN * DINNER;

    for (int l = 0; l < SEQLEN; l++) {
        size_t lh = (size_t)l * HALF;
        float u0  = up [lh + dd0];
        float u1  = up [lh + dd1];
        float dt0 = dtp[lh + dd0];
        float dt1 = dtp[lh + dd1];
        size_t lo = (size_t)l * XDBL;
        float Bv = bp[lo];
        float Cv = bp[lo + DSTATE];

        h0 = fmaf(__expf(dt0 * a0), h0, dt0 * u0 * Bv);
        h1 = fmaf(__expf(dt1 * a1), h1, dt1 * u1 * Bv);

        float p0 = h0 * Cv;
        float p1 = h1 * Cv;
        p0 += __shfl_xor_sync(0xffffffffu, p0, 8);
        p1 += __shfl_xor_sync(0xffffffffu, p1, 8);
        p0 += __shfl_xor_sync(0xffffffffu, p0, 4);
        p1 += __shfl_xor_sync(0xffffffffu, p1, 4);
        p0 += __shfl_xor_sync(0xffffffffu, p0, 2);
        p1 += __shfl_xor_sync(0xffffffffu, p1, 2);
        p0 += __shfl_xor_sync(0xffffffffu, p0, 1);
        p1 += __shfl_xor_sync(0xffffffffu, p1, 1);
        if (n == 0) {
            float* yr = yp + (size_t)l * DINNER;
            yr[dd0] = fmaf(u0, D0, p0);
            yr[dd1] = fmaf(u1, D1, p1);
        }
    }
}

// ---------------- fused3: scan (256 blocks, FIRST) || z-GEMM slice B ----------
__global__ __launch_bounds__(256) void fused3_k(
    const float* __restrict__ Dvec,
    const float* __restrict__ W_out, const float* __restrict__ b_out,
    float* __restrict__ out)
{
    __shared__ float smem[16 * 132 + 16 * 128];   // 4160 floats
    if (blockIdx.x < 256) {
        scan_blk(blockIdx.x, Dvec);
    } else {
        gemm_z_blk(smem, smem + 16 * 132, ZSPLIT1 + blockIdx.x - 256,
                   W_out, b_out, out);
    }
}

// ---------------- launch ------------------------------------------------------
extern "C" void kernel_launch(void* const* d_in, const int* in_sizes, int n_in,
                              void* d_out, int out_size)
{
    const float* x       = (const float*)d_in[0];
    const float* W_in    = (const float*)d_in[1];
    const float* conv_xk = (const float*)d_in[2];
    const float* conv_zk = (const float*)d_in[3];
    const float* W_xproj = (const float*)d_in[4];
    const float* W_dt    = (const float*)d_in[5];
    const float* b_dt    = (const float*)d_in[6];
    const float* A_log   = (const float*)d_in[7];
    const float* Dvec    = (const float*)d_in[8];
    const float* W_out   = (const float*)d_in[9];
    const float* b_out   = (const float*)d_in[10];
    float* out = (float*)d_out;

    aprep_k<<<(HALF * DSTATE + 255) / 256, 256>>>(A_log);

    // xz = x @ W_in
    gemm_in_k<<<dim3(DINNER / 128, NTOK / 128), 256>>>(x, W_in);

    // depthwise conv + silu (produces xh and z)
    conv_silu_k<<<(size_t)NTOK * HALF / 256, 256>>>(conv_xk, conv_zk);

    // fused1: xproj (128 blocks) || z-GEMM blocks [0, ZSPLIT1)
    fused1_k<<<128 + ZSPLIT1, 256>>>(W_xproj, W_out, b_out, out);

    // delta = softplus(x_dbl[:, :64] @ W_dt + 2*b_dt)
    dtproj_k<<<dim3(HALF / 64, NTOK / 64), 256>>>(W_dt, b_dt);

    // fused3: scan (256 blocks) || z-GEMM blocks [ZSPLIT1, 1024)
    fused3_k<<<256 + (1024 - ZSPLIT1), 256>>>(Dvec, W_out, b_out, out);

    // out += y @ W_out[:HALF]
    gemm_y_k<<<dim3(DMODEL / 128, NTOK / 128), 256>>>(W_out, out);
}

// round 16
// speedup vs baseline: 1.2010x; 1.2010x over previous
#include <cuda_runtime.h>
#include <math.h>
#include <stdint.h>

#define BATCH   8
#define SEQLEN  2048
#define DMODEL  1024
#define HALF    1024
#define DINNER  2048
#define DSTATE  16
#define DTRANK  64
#define XDBL    96          // DTRANK + 2*DSTATE
#define NTOK    (BATCH*SEQLEN)   // 16384

// ---------------- scratch (static device globals: allocation-guard safe) ----
static __device__ float g_xz   [(size_t)NTOK * DINNER];  // xz = x @ W_in
static __device__ float g_xh   [(size_t)NTOK * HALF];    // silu(conv(xh))
static __device__ float g_delta[(size_t)NTOK * HALF];    // softplus(dt)
static __device__ float g_xdbl [(size_t)NTOK * XDBL];    // [dt_r | B | C]
static __device__ float g_ycat [(size_t)NTOK * DINNER];  // [y | silu(conv(z))]
static __device__ float g_A    [HALF * DSTATE];          // -exp(A_log)

// ---------------- helpers ---------------------------------------------------
__device__ __forceinline__ float siluf(float v) {
    return v / (1.0f + __expf(-v));
}
__device__ __forceinline__ unsigned long long pack2(float x, float y) {
    unsigned long long r;
    asm("mov.b64 %0, {%1, %2};" : "=l"(r) : "f"(x), "f"(y));
    return r;
}
__device__ __forceinline__ void fma2(unsigned long long& d,
                                     unsigned long long a, unsigned long long b) {
    asm("fma.rn.f32x2 %0, %1, %2, %0;" : "+l"(d) : "l"(a), "l"(b));
}
__device__ __forceinline__ float2 unpack2(unsigned long long v) {
    float x, y;
    asm("mov.b64 {%0, %1}, %2;" : "=f"(x), "=f"(y) : "l"(v));
    return make_float2(x, y);
}

// ---------------- A = -exp(A_log) -------------------------------------------
__global__ void aprep_k(const float* __restrict__ A_log) {
    int i = blockIdx.x * blockDim.x + threadIdx.x;
    if (i < HALF * DSTATE) g_A[i] = -__expf(A_log[i]);
}

// ---------------- double-buffered 128x128x16 SGEMM core (f32x2 math) --------
// C[bm:+128, bn:+128] (+)= A[M,K](lda) @ B[K,N] (+ bias).
// Per iter: prefetch next tile to regs -> compute current -> store -> 1 sync.
__device__ __forceinline__ void sgemm_db(
    float* __restrict__ As,   // 2 x 16*132 floats
    float* __restrict__ Bs,   // 2 x 16*128 floats
    const float* __restrict__ A, int lda,
    const float* __restrict__ B,
    const float* __restrict__ bias, float* __restrict__ C, int accum,
    int bm, int bn, int N, int K)
{
    const int BK = 16;
    int tid = threadIdx.x;
    int tx = tid & 15;
    int ty = tid >> 4;

    unsigned long long acc2[8][4];
#pragma unroll
    for (int i = 0; i < 8; i++)
#pragma unroll
        for (int j = 0; j < 4; j++) acc2[i][j] = 0ULL;

    int a_row = tid >> 2;           // 0..63
    int a_col = (tid & 3) << 2;     // 0,4,8,12
    int b_row = tid >> 5;           // 0..7
    int b_col = (tid & 31) << 2;    // 0..124

    const float* Aptr = A + (size_t)bm * lda;
    const float* Bptr = B + bn;

    float4 va[2], vb[2];
    // tile 0 -> regs -> smem buf 0
#pragma unroll
    for (int r = 0; r < 2; r++)
        va[r] = *(const float4*)(Aptr + (size_t)(a_row + r * 64) * lda + a_col);
#pragma unroll
    for (int r = 0; r < 2; r++)
        vb[r] = *(const float4*)(Bptr + (size_t)(b_row + r * 8) * N + b_col);
#pragma unroll
    for (int r = 0; r < 2; r++) {
        int row = a_row + r * 64;
        As[(a_col + 0) * 132 + row] = va[r].x;
        As[(a_col + 1) * 132 + row] = va[r].y;
        As[(a_col + 2) * 132 + row] = va[r].z;
        As[(a_col + 3) * 132 + row] = va[r].w;
    }
#pragma unroll
    for (int r = 0; r < 2; r++)
        *(float4*)(&Bs[(b_row + r * 8) * 128 + b_col]) = vb[r];
    __syncthreads();

    const int niter = K / BK;
    for (int i = 0; i < niter; i++) {
        const int cur = i & 1, nxt = cur ^ 1;
        float* Ac = As + cur * (16 * 132);
        float* Bc = Bs + cur * (16 * 128);

        if (i + 1 < niter) {        // prefetch next tile to regs (overlaps FMA)
            int k0 = (i + 1) * BK;
#pragma unroll
            for (int r = 0; r < 2; r++)
                va[r] = *(const float4*)(Aptr + (size_t)(a_row + r * 64) * lda + k0 + a_col);
#pragma unroll
            for (int r = 0; r < 2; r++)
                vb[r] = *(const float4*)(Bptr + (size_t)(k0 + b_row + r * 8) * N + b_col);
        }

#pragma unroll
        for (int k = 0; k < BK; k++) {
            float4 a0 = *(const float4*)(&Ac[k * 132 + ty * 8]);
            float4 a1 = *(const float4*)(&Ac[k * 132 + ty * 8 + 4]);
            float4 b0 = *(const float4*)(&Bc[k * 128 + tx * 8]);
            float4 b1 = *(const float4*)(&Bc[k * 128 + tx * 8 + 4]);
            unsigned long long bp[4];
            bp[0] = pack2(b0.x, b0.y);
            bp[1] = pack2(b0.z, b0.w);
            bp[2] = pack2(b1.x, b1.y);
            bp[3] = pack2(b1.z, b1.w);
            float af[8] = {a0.x, a0.y, a0.z, a0.w, a1.x, a1.y, a1.z, a1.w};
#pragma unroll
            for (int q = 0; q < 8; q++) {
                unsigned long long ap = pack2(af[q], af[q]);
                fma2(acc2[q][0], ap, bp[0]);
                fma2(acc2[q][1], ap, bp[1]);
                fma2(acc2[q][2], ap, bp[2]);
                fma2(acc2[q][3], ap, bp[3]);
            }
        }

        if (i + 1 < niter) {        // store prefetched tile to alternate buffer
            float* An = As + nxt * (16 * 132);
            float* Bn = Bs + nxt * (16 * 128);
#pragma unroll
            for (int r = 0; r < 2; r++) {
                int row = a_row + r * 64;
                An[(a_col + 0) * 132 + row] = va[r].x;
                An[(a_col + 1) * 132 + row] = va[r].y;
                An[(a_col + 2) * 132 + row] = va[r].z;
                An[(a_col + 3) * 132 + row] = va[r].w;
            }
#pragma unroll
            for (int r = 0; r < 2; r++)
                *(float4*)(&Bn[(b_row + r * 8) * 128 + b_col]) = vb[r];
        }
        __syncthreads();
    }

#pragma unroll
    for (int i = 0; i < 8; i++) {
        int row = bm + ty * 8 + i;
#pragma unroll
        for (int j = 0; j < 2; j++) {
            int col = bn + tx * 8 + j * 4;
            float2 p0 = unpack2(acc2[i][j * 2]);
            float2 p1 = unpack2(acc2[i][j * 2 + 1]);
            float4 v = make_float4(p0.x, p0.y, p1.x, p1.y);
            float* cp = C + (size_t)row * N + col;
            if (accum) {
                float4 c = *(float4*)cp;
                v.x += c.x; v.y += c.y; v.z += c.z; v.w += c.w;
            }
            if (bias) {
                v.x += bias[col];   v.y += bias[col+1];
                v.z += bias[col+2]; v.w += bias[col+3];
            }
            *(float4*)cp = v;
        }
    }
}

__global__ __launch_bounds__(256, 2) void gemm_in_k(
    const float* __restrict__ x, const float* __restrict__ W_in)
{
    __shared__ float As[2 * 16 * 132];
    __shared__ float Bs[2 * 16 * 128];
    sgemm_db(As, Bs, x, DMODEL, W_in, nullptr, g_xz, 0,
             blockIdx.y * 128, blockIdx.x * 128, DINNER, DMODEL);
}

// out = z @ W_out[HALF:, :] + b_out   (z = g_ycat[:, HALF:])
__global__ __launch_bounds__(256, 2) void gemm_z_k(
    const float* __restrict__ W_out, const float* __restrict__ b_out,
    float* __restrict__ out)
{
    __shared__ float As[2 * 16 * 132];
    __shared__ float Bs[2 * 16 * 128];
    sgemm_db(As, Bs, g_ycat + HALF, DINNER, W_out + (size_t)HALF * DMODEL,
             b_out, out, 0, blockIdx.y * 128, blockIdx.x * 128, DMODEL, HALF);
}

// out += y @ W_out[:HALF, :]          (y = g_ycat[:, :HALF])
__global__ __launch_bounds__(256, 2) void gemm_y_k(
    const float* __restrict__ W_out, float* __restrict__ out)
{
    __shared__ float As[2 * 16 * 132];
    __shared__ float Bs[2 * 16 * 128];
    sgemm_db(As, Bs, g_ycat, DINNER, W_out, nullptr, out, 1,
             blockIdx.y * 128, blockIdx.x * 128, DMODEL, HALF);
}

// ---------------- depthwise conv1d(width 4, SAME: pad_lo=1) + SiLU ----------
__global__ __launch_bounds__(256) void conv_silu_k(
    const float* __restrict__ kx, const float* __restrict__ kz)
{
    int idx = blockIdx.x * 256 + threadIdx.x;       // over NTOK*HALF
    int c  = idx & (HALF - 1);
    int bl = idx >> 10;
    int l  = bl & (SEQLEN - 1);

    float accx = 0.0f, accz = 0.0f;
    const float* base = g_xz + (size_t)bl * DINNER;
#pragma unroll
    for (int w = 0; w < 4; w++) {
        int dl = w - 1;
        int ll = l + dl;
        if (ll >= 0 && ll < SEQLEN) {
            const float* p = base + (ptrdiff_t)dl * DINNER;
            accx = fmaf(p[c],        kx[w * HALF + c], accx);
            accz = fmaf(p[HALF + c], kz[w * HALF + c], accz);
        }
    }
    g_xh  [(size_t)bl * HALF   + c]        = siluf(accx);
    g_ycat[(size_t)bl * DINNER + HALF + c] = siluf(accz);
}

// ---------------- x_dbl = xh @ W_xproj (128-row tiles, proven R9) -------------
__global__ __launch_bounds__(256) void xproj_k(const float* __restrict__ W)
{
    __shared__ float As[32 * 128];  // [k][m]
    __shared__ float Ws[32 * 96];   // [k][n]
    int tid = threadIdx.x;
    int bm = blockIdx.x * 128;
    int tx = tid & 15;   // 6 cols each
    int ty = tid >> 4;   // 8 rows each

    float acc[8][6];
#pragma unroll
    for (int i = 0; i < 8; i++)
#pragma unroll
        for (int j = 0; j < 6; j++) acc[i][j] = 0.0f;

    for (int k0 = 0; k0 < HALF; k0 += 32) {
        for (int i = tid; i < 128 * 32; i += 256) {
            int m = i >> 5, k = i & 31;
            As[k * 128 + m] = g_xh[(size_t)(bm + m) * HALF + k0 + k];
        }
        for (int i = tid; i < 32 * 96; i += 256) {
            int k = i / 96, n = i - k * 96;
            Ws[k * 96 + n] = W[(size_t)(k0 + k) * XDBL + n];
        }
        __syncthreads();
#pragma unroll 8
        for (int k = 0; k < 32; k++) {
            float af[8], wf[6];
#pragma unroll
            for (int i = 0; i < 8; i++) af[i] = As[k * 128 + ty * 8 + i];
#pragma unroll
            for (int j = 0; j < 6; j++) wf[j] = Ws[k * 96 + tx * 6 + j];
#pragma unroll
            for (int i = 0; i < 8; i++)
#pragma unroll
                for (int j = 0; j < 6; j++)
                    acc[i][j] = fmaf(af[i], wf[j], acc[i][j]);
        }
        __syncthreads();
    }
#pragma unroll
    for (int i = 0; i < 8; i++)
#pragma unroll
        for (int j = 0; j < 6; j++)
            g_xdbl[(size_t)(bm + ty * 8 + i) * XDBL + tx * 6 + j] = acc[i][j];
}

// ---------------- delta = softplus(x_dbl[:, :64] @ W_dt + 2*b_dt) -----------
__global__ __launch_bounds__(256) void dtproj_k(
    const float* __restrict__ Wdt, const float* __restrict__ bdt)
{
    __shared__ float As[64 * 64];
    __shared__ float Ws[64 * 64];
    int tid = threadIdx.x;
    int bm = blockIdx.y * 64;
    int bn = blockIdx.x * 64;
    int tx = tid & 15;
    int ty = tid >> 4;

    for (int i = tid; i < 64 * 64; i += 256) {
        int m = i >> 6, k = i & 63;
        As[k * 64 + m] = g_xdbl[(size_t)(bm + m) * XDBL + k];
    }
    for (int i = tid; i < 64 * 64; i += 256) {
        int k = i >> 6, n = i & 63;
        Ws[k * 64 + n] = Wdt[(size_t)k * HALF + bn + n];
    }
    __syncthreads();

    float acc[4][4];
#pragma unroll
    for (int i = 0; i < 4; i++)
#pragma unroll
        for (int j = 0; j < 4; j++) acc[i][j] = 0.0f;

#pragma unroll 16
    for (int k = 0; k < 64; k++) {
        float af[4], wf[4];
#pragma unroll
        for (int i = 0; i < 4; i++) af[i] = As[k * 64 + ty * 4 + i];
#pragma unroll
        for (int j = 0; j < 4; j++) wf[j] = Ws[k * 64 + tx * 4 + j];
#pragma unroll
        for (int i = 0; i < 4; i++)
#pragma unroll
            for (int j = 0; j < 4; j++)
                acc[i][j] = fmaf(af[i], wf[j], acc[i][j]);
    }

#pragma unroll
    for (int i = 0; i < 4; i++) {
        int row = bm + ty * 4 + i;
#pragma unroll
        for (int j = 0; j < 4; j++) {
            int col = bn + tx * 4 + j;
            float v = acc[i][j] + 2.0f * bdt[col];
            float sp = (v > 25.0f) ? v : log1pf(__expf(v));
            g_delta[(size_t)row * HALF + col] = sp;
        }
    }
}

// ---------------- selective scan (next-l input prefetch) ----------------------
__global__ __launch_bounds__(256) void scan_k(const float* __restrict__ Dvec)
{
    int n  = threadIdx.x & 15;
    int dd = blockIdx.x * 16 + (threadIdx.x >> 4);
    int b  = blockIdx.y;

    float a  = g_A[dd * DSTATE + n];
    float Dd = Dvec[dd];
    float h  = 0.0f;

    const float* up  = g_xh    + (size_t)b * SEQLEN * HALF  + dd;
    const float* dtp = g_delta + (size_t)b * SEQLEN * HALF  + dd;
    const float* bp  = g_xdbl  + (size_t)b * SEQLEN * XDBL  + DTRANK + n;
    float*       yp  = g_ycat  + (size_t)b * SEQLEN * DINNER + dd;

    float u_n  = up [0];
    float dt_n = dtp[0];
    float Bv_n = bp [0];
    float Cv_n = bp [DSTATE];

    for (int l = 0; l < SEQLEN; l++) {
        float u = u_n, dt = dt_n, Bv = Bv_n, Cv = Cv_n;
        if (l + 1 < SEQLEN) {               // prefetch next-l inputs
            size_t lh = (size_t)(l + 1) * HALF;
            size_t lx = (size_t)(l + 1) * XDBL;
            u_n  = up [lh];
            dt_n = dtp[lh];
            Bv_n = bp [lx];
            Cv_n = bp [lx + DSTATE];
        }

        float dA = __expf(dt * a);
        h = fmaf(dA, h, dt * u * Bv);

        float p = h * Cv;
        p += __shfl_xor_sync(0xffffffffu, p, 8);
        p += __shfl_xor_sync(0xffffffffu, p, 4);
        p += __shfl_xor_sync(0xffffffffu, p, 2);
        p += __shfl_xor_sync(0xffffffffu, p, 1);
        if (n == 0) yp[(size_t)l * DINNER] = fmaf(u, Dd, p);
    }
}

// ---------------- launch ------------------------------------------------------
extern "C" void kernel_launch(void* const* d_in, const int* in_sizes, int n_in,
                              void* d_out, int out_size)
{
    const float* x       = (const float*)d_in[0];
    const float* W_in    = (const float*)d_in[1];
    const float* conv_xk = (const float*)d_in[2];
    const float* conv_zk = (const float*)d_in[3];
    const float* W_xproj = (const float*)d_in[4];
    const float* W_dt    = (const float*)d_in[5];
    const float* b_dt    = (const float*)d_in[6];
    const float* A_log   = (const float*)d_in[7];
    const float* Dvec    = (const float*)d_in[8];
    const float* W_out   = (const float*)d_in[9];
    const float* b_out   = (const float*)d_in[10];
    float* out = (float*)d_out;

    aprep_k<<<(HALF * DSTATE + 255) / 256, 256>>>(A_log);

    // xz = x @ W_in  (double-buffered)
    gemm_in_k<<<dim3(DINNER / 128, NTOK / 128), 256>>>(x, W_in);

    // depthwise conv + silu
    conv_silu_k<<<(size_t)NTOK * HALF / 256, 256>>>(conv_xk, conv_zk);

    // x_dbl = xh @ W_xproj
    xproj_k<<<NTOK / 128, 256>>>(W_xproj);

    // delta = softplus(x_dbl[:, :64] @ W_dt + 2*b_dt)
    dtproj_k<<<dim3(HALF / 64, NTOK / 64), 256>>>(W_dt, b_dt);

    // selective scan -> g_ycat[:, :HALF]
    scan_k<<<dim3(HALF / 16, BATCH), 256>>>(Dvec);

    // out = z @ W_out[HALF:] + b_out; then out += y @ W_out[:HALF]
    gemm_z_k<<<dim3(DMODEL / 128, NTOK / 128), 256>>>(W_out, b_out, out);
    gemm_y_k<<<dim3(DMODEL / 128, NTOK / 128), 256>>>(W_out, out);
}